// round 1
// baseline (speedup 1.0000x reference)
#include <cuda_runtime.h>

#define B_  4
#define Qn  1024
#define Kn  1024
#define QS  256
#define KSZ 256
#define Hn  32
#define VD  256
#define TQ  8
#define TK  128

// Device-global scratch (no runtime allocation allowed)
__device__ float g_fq[B_ * Qn * Hn];
__device__ float g_fk[B_ * Kn * Hn];

// ---------------- helpers ----------------

__device__ __forceinline__ float fast_tanh(float x) {
    // tanh(x) = 1 - 2/(exp(2x)+1), robust at +/-inf. ex2/rcp approx err ~2^-22.
    float e;
    asm("ex2.approx.f32 %0, %1;" : "=f"(e) : "f"(x * 2.885390081777927f)); // 2*log2(e)
    float r;
    asm("rcp.approx.f32 %0, %1;" : "=f"(r) : "f"(e + 1.0f));
    return fmaf(-2.0f, r, 1.0f);
}

__device__ __forceinline__ float warp_max(float v) {
    #pragma unroll
    for (int o = 16; o > 0; o >>= 1) v = fmaxf(v, __shfl_xor_sync(0xFFFFFFFFu, v, o));
    return v;
}
__device__ __forceinline__ float warp_sum(float v) {
    #pragma unroll
    for (int o = 16; o > 0; o >>= 1) v += __shfl_xor_sync(0xFFFFFFFFu, v, o);
    return v;
}

__device__ __forceinline__ unsigned long long pack2(float lo, float hi) {
    unsigned long long r;
    asm("mov.b64 %0, {%1, %2};" : "=l"(r) : "f"(lo), "f"(hi));
    return r;
}
__device__ __forceinline__ void unpack2(unsigned long long a, float& lo, float& hi) {
    asm("mov.b64 {%0, %1}, %2;" : "=f"(lo), "=f"(hi) : "l"(a));
}
__device__ __forceinline__ void fma2(unsigned long long& a, unsigned long long v, unsigned long long p) {
    asm("fma.rn.f32x2 %0, %1, %2, %0;" : "+l"(a) : "l"(v), "l"(p));
}
__device__ __forceinline__ void mul2(unsigned long long& a, unsigned long long s) {
    asm("mul.rn.f32x2 %0, %0, %1;" : "+l"(a) : "l"(s));
}

// ---------------- kernel 1: projections fq = q@Wq+bq, fk = k@Wk+bk ----------------

__global__ __launch_bounds__(256)
void proj_kernel(const float* __restrict__ queries, const float* __restrict__ keys,
                 const float* __restrict__ Wq, const float* __restrict__ bq,
                 const float* __restrict__ Wk, const float* __restrict__ bk) {
    __shared__ float xs[8][QS];
    int w = threadIdx.x >> 5, lane = threadIdx.x & 31;
    int row = blockIdx.x * 8 + w;

    const float* src; const float* W; const float* bias; float* dst;
    if (row < B_ * Qn) {
        src = queries + (size_t)row * QS; W = Wq; bias = bq; dst = g_fq + (size_t)row * Hn;
    } else {
        int r2 = row - B_ * Qn;
        src = keys + (size_t)r2 * KSZ; W = Wk; bias = bk; dst = g_fk + (size_t)r2 * Hn;
    }

    #pragma unroll
    for (int r = 0; r < QS / 32; r++) xs[w][lane + 32 * r] = src[lane + 32 * r];
    __syncwarp();

    float sum = 0.0f;
    #pragma unroll 8
    for (int j = 0; j < QS; j++) sum = fmaf(xs[w][j], W[j * Hn + lane], sum);
    dst[lane] = sum + bias[lane];
}

// ---------------- kernel 2: fused additive attention ----------------
// grid = (Q/TQ, B), block = 256. Warp w: phase A owns q-row w; phase B owns k-slice w.

__global__ __launch_bounds__(256)
void attn_kernel(const float* __restrict__ values, const int* __restrict__ valid_lens,
                 const float* __restrict__ wvec, float* __restrict__ out) {
    __shared__ float fk_s[TK * 36];   // [k][h], row stride 36 floats (9 float4) -> conflict-free
    __shared__ float pT[TK * 9];      // [k][q], row stride 9 -> conflict-free scalar writes
    __shared__ float fq_s[TQ * 32];
    __shared__ float wv_s[32];
    __shared__ float scale_s[TQ];
    __shared__ float l_s[TQ];

    const int tid  = threadIdx.x;
    const int w    = tid >> 5;
    const int lane = tid & 31;
    const int b    = blockIdx.y;
    const int q0   = blockIdx.x * TQ;
    const int valid = valid_lens[b];

    fq_s[w * 32 + lane] = g_fq[((size_t)(b * Qn + q0 + w)) * Hn + lane];
    if (tid < 32) wv_s[tid] = wvec[tid];

    float m_run = -1e30f, l_run = 0.0f;
    unsigned long long acc[TQ][4];
    #pragma unroll
    for (int q = 0; q < TQ; q++)
        #pragma unroll
        for (int j = 0; j < 4; j++) acc[q][j] = 0ull;

    const float* vbatch = values + (size_t)b * Kn * VD;
    const int nchunks = (valid + TK - 1) / TK;

    for (int c = 0; c < nchunks; c++) {
        const int kb = c * TK;
        __syncthreads();  // prior-phase consumers of fk_s / pT are done

        // Load fk chunk: 1024 float4s, 4 per thread, coalesced LDG -> padded smem
        {
            const float4* src = (const float4*)(g_fk + ((size_t)(b * Kn + kb)) * Hn);
            float4* dstp = (float4*)fk_s;
            #pragma unroll
            for (int r = 0; r < 4; r++) {
                int idx = tid + 256 * r;
                int k = idx >> 3, hb = idx & 7;
                dstp[k * 9 + hb] = src[idx];
            }
        }
        __syncthreads();

        // -------- Phase A: scores for q=w, k=lane+32i (stay in registers) --------
        float sacc[4] = {0.f, 0.f, 0.f, 0.f};
        {
            const float4* fq4 = (const float4*)(fq_s + w * 32);
            const float4* wv4 = (const float4*)wv_s;
            const float4* fk4 = (const float4*)fk_s;
            #pragma unroll
            for (int hb = 0; hb < 8; hb++) {
                float4 a = fq4[hb];
                float4 g = wv4[hb];
                #pragma unroll
                for (int i = 0; i < 4; i++) {
                    float4 f = fk4[(lane + 32 * i) * 9 + hb];
                    sacc[i] = fmaf(g.x, fast_tanh(a.x + f.x), sacc[i]);
                    sacc[i] = fmaf(g.y, fast_tanh(a.y + f.y), sacc[i]);
                    sacc[i] = fmaf(g.z, fast_tanh(a.z + f.z), sacc[i]);
                    sacc[i] = fmaf(g.w, fast_tanh(a.w + f.w), sacc[i]);
                }
            }
            #pragma unroll
            for (int i = 0; i < 4; i++)
                if (kb + lane + 32 * i >= valid) sacc[i] = -1e30f;
        }

        // -------- Online softmax (per-warp, warp w owns row q=w) --------
        {
            float mx = fmaxf(fmaxf(sacc[0], sacc[1]), fmaxf(sacc[2], sacc[3]));
            mx = warp_max(mx);
            float m_new = fmaxf(m_run, mx);
            float sc = __expf(m_run - m_new);
            m_run = m_new;
            float ps = 0.0f;
            #pragma unroll
            for (int i = 0; i < 4; i++) {
                float p = __expf(sacc[i] - m_new);
                ps += p;
                pT[(lane + 32 * i) * 9 + w] = p;
            }
            ps = warp_sum(ps);
            l_run = l_run * sc + ps;
            if (lane == 0) scale_s[w] = sc;
        }
        __syncthreads();

        // -------- Phase B: P@V. warp w = k-slice [w*16, w*16+16), lanes = v --------
        {
            #pragma unroll
            for (int q = 0; q < TQ; q++) {
                unsigned long long s2 = pack2(scale_s[q], scale_s[q]);
                #pragma unroll
                for (int j = 0; j < 4; j++) mul2(acc[q][j], s2);
            }
            const int kloc0 = w * 16;
            #pragma unroll 4
            for (int kk = 0; kk < 16; kk++) {
                int kg = kb + kloc0 + kk;
                if (kg >= valid) break;
                const ulonglong2* vrow = (const ulonglong2*)(vbatch + (size_t)kg * VD);
                ulonglong2 v0 = __ldg(&vrow[lane * 2]);
                ulonglong2 v1 = __ldg(&vrow[lane * 2 + 1]);
                const float* prow = pT + (kloc0 + kk) * 9;
                #pragma unroll
                for (int q = 0; q < TQ; q++) {
                    float p = prow[q];
                    unsigned long long p2 = pack2(p, p);
                    fma2(acc[q][0], v0.x, p2);
                    fma2(acc[q][1], v0.y, p2);
                    fma2(acc[q][2], v1.x, p2);
                    fma2(acc[q][3], v1.y, p2);
                }
            }
        }
    }

    // -------- Epilogue: reduce partial acc across the 8 k-slice warps --------
    if (lane == 0) l_s[w] = l_run;
    __syncthreads();

    float* buf = fk_s;  // reuse (4608 floats >= 2048)
    #pragma unroll
    for (int q = 0; q < TQ; q++) {
        #pragma unroll
        for (int j = 0; j < 4; j++) {
            float lo, hi;
            unpack2(acc[q][j], lo, hi);
            buf[w * 256 + lane * 8 + 2 * j]     = lo;
            buf[w * 256 + lane * 8 + 2 * j + 1] = hi;
        }
        __syncthreads();
        float tot = 0.0f;
        #pragma unroll
        for (int g = 0; g < 8; g++) tot += buf[g * 256 + tid];
        float inv = 1.0f / l_s[q];
        out[((size_t)(b * Qn + q0 + q)) * VD + tid] = tot * inv;
        __syncthreads();
    }
}

// ---------------- launch ----------------

extern "C" void kernel_launch(void* const* d_in, const int* in_sizes, int n_in,
                              void* d_out, int out_size) {
    const float* keys       = (const float*)d_in[0];
    const float* queries    = (const float*)d_in[1];
    const float* values     = (const float*)d_in[2];
    const int*   valid_lens = (const int*)d_in[3];
    const float* W_q        = (const float*)d_in[4];
    const float* b_q        = (const float*)d_in[5];
    const float* W_k        = (const float*)d_in[6];
    const float* b_k        = (const float*)d_in[7];
    const float* w_v        = (const float*)d_in[8];
    // b_v (d_in[9]) is softmax-invariant: adding a constant to all scores does
    // not change the softmax weights, so it is intentionally unused.
    float* out = (float*)d_out;

    int total_rows = B_ * (Qn + Kn);            // 8192
    proj_kernel<<<total_rows / 8, 256>>>(queries, keys, W_q, b_q, W_k, b_k);

    dim3 grid(Qn / TQ, B_);
    attn_kernel<<<grid, 256>>>(values, valid_lens, w_v, out);
}